// round 1
// baseline (speedup 1.0000x reference)
#include <cuda_runtime.h>
#include <cstdint>
#include <cstddef>

// ---------------------------------------------------------------------------
// SNN with cochlea front-end.  B=64, T=500, IN=256, HID=512, OUT=35.
//
// Strategy: one persistent CTA per batch element (64 CTAs, zero inter-CTA
// sync).  All membrane state lives in registers (thread n owns neuron n of
// every layer).  Layer 1 uses exact 5-bit integer weight levels in SMEM
// (128 KB) driven by a compacted cochlea-spike list.  Layers 2/3/4 use the
// rowsum-minus-complement identity: hidden spikes saturate to all-ones, so
// the big GEMMs collapse to a precomputed row sum with (rare) sparse
// corrections read from L2-resident transposed quantized weights.
// ---------------------------------------------------------------------------

namespace {
constexpr int T_STEPS = 500;
constexpr int BATCH   = 64;
constexpr int N_IN    = 256;
constexpr int N_HID   = 512;
constexpr int N_OUT   = 35;
// Quantization scale, computed exactly as the reference does in float64 then
// used as float32: scale = (1.0 - 0.001) / (2**5 - 1)
constexpr float SCALEF = (float)((1.0 - 0.001) / 31.0);

constexpr size_t SPK_HID = (size_t)T_STEPS * BATCH * N_HID;  // one hidden spike tensor
constexpr size_t SPK_OUT = (size_t)T_STEPS * BATCH * N_OUT;  // spk4 / mem4 tensor
}  // namespace

// Scratch (static device globals; no runtime allocation)
__device__ unsigned char g_w1q[N_IN * N_HID];   // layer-1 levels, transposed [k][n]
__device__ float g_q2T[N_HID * N_HID];          // quantized W2, transposed [k][n]
__device__ float g_q3T[N_HID * N_HID];          // quantized W3, transposed [k][n]
__device__ float g_q4T[N_HID * N_OUT];          // quantized W4, transposed [k][o]
__device__ float g_rs2[N_HID];
__device__ float g_rs3[N_HID];
__device__ float g_rs4[N_OUT];

// Exact replication of the reference fake_quant (fp32 ops, round-half-even,
// no FMA contraction).
__device__ __forceinline__ float quantw(float w) {
    float wc = fminf(fmaxf(w, 0.001f), 1.0f);
    float l  = rintf((wc - 0.001f) / SCALEF);       // IEEE fp32 division
    return __fadd_rn(__fmul_rn(l, SCALEF), 0.001f); // l*scale + W_MIN, two roundings
}

// ---------------------------------------------------------------------------
// Prep kernel 1: quantize + transpose all weight matrices.
// ---------------------------------------------------------------------------
__global__ void prep_quant(const float* __restrict__ W1, const float* __restrict__ W2,
                           const float* __restrict__ W3, const float* __restrict__ W4) {
    int idx = blockIdx.x * blockDim.x + threadIdx.x;
    if (idx < N_HID * N_IN) {               // W1: (512,256) row-major -> levels [k][n]
        int n = idx / N_IN, k = idx % N_IN;
        float wc = fminf(fmaxf(W1[idx], 0.001f), 1.0f);
        float l  = rintf((wc - 0.001f) / SCALEF);
        g_w1q[k * N_HID + n] = (unsigned char)(int)l;
    }
    if (idx < N_HID * N_HID) {              // W2 / W3: (512,512)
        int n = idx / N_HID, k = idx % N_HID;
        g_q2T[k * N_HID + n] = quantw(W2[idx]);
        g_q3T[k * N_HID + n] = quantw(W3[idx]);
    }
    if (idx < N_OUT * N_HID) {              // W4: (35,512)
        int o = idx / N_HID, k = idx % N_HID;
        g_q4T[k * N_OUT + o] = quantw(W4[idx]);
    }
}

// ---------------------------------------------------------------------------
// Prep kernel 2: row sums of the quantized matrices (ascending-k order).
// ---------------------------------------------------------------------------
__global__ void prep_rowsum() {
    int n = blockIdx.x * blockDim.x + threadIdx.x;
    if (n < N_HID) {
        float s2 = 0.f, s3 = 0.f;
        for (int k = 0; k < N_HID; ++k) {
            s2 = __fadd_rn(s2, g_q2T[k * N_HID + n]);
            s3 = __fadd_rn(s3, g_q3T[k * N_HID + n]);
        }
        g_rs2[n] = s2;
        g_rs3[n] = s3;
        if (n < N_OUT) {
            float s4 = 0.f;
            for (int k = 0; k < N_HID; ++k) s4 = __fadd_rn(s4, g_q4T[k * N_OUT + n]);
            g_rs4[n] = s4;
        }
    }
}

// ---------------------------------------------------------------------------
// Main persistent kernel: one CTA per batch element, 512 threads.
// ---------------------------------------------------------------------------
__global__ void __launch_bounds__(512, 1) snn_main(
    const float* __restrict__ x, const float* __restrict__ Wch,
    const float* __restrict__ cbetas,
    const float* __restrict__ pb1, const float* __restrict__ pb2,
    const float* __restrict__ pb3, const float* __restrict__ pb4,
    float* __restrict__ out)
{
    const int b    = blockIdx.x;
    const int tid  = threadIdx.x;
    const int lane = tid & 31;
    const int warp = tid >> 5;
    const unsigned ltm = (1u << lane) - 1u;

    extern __shared__ unsigned char sw1[];   // 256*512 = 128 KB of uint8 levels
    __shared__ unsigned s_chmask[8];
    __shared__ int      s_chlist[N_IN];      // pre-multiplied row offsets (k*512)
    __shared__ unsigned s_zmask[16];
    __shared__ int      s_zlist[N_HID];

    // Cooperative load of layer-1 levels into SMEM (uint4 vectorized).
    {
        const uint4* src = (const uint4*)g_w1q;
        uint4*       dst = (uint4*)sw1;
        for (int i = tid; i < (N_IN * N_HID) / 16; i += 512) dst[i] = src[i];
    }

    const float beta1 = fminf(fmaxf(pb1[0], 0.f), 1.f);
    const float beta2 = fminf(fmaxf(pb2[0], 0.f), 1.f);
    const float beta3 = fminf(fmaxf(pb3[0], 0.f), 1.f);
    const float beta4 = fminf(fmaxf(pb4[0], 0.f), 1.f);

    float wch = 0.f, bch = 0.f;
    if (tid < N_IN) {
        wch = Wch[tid];
        bch = fminf(fmaxf(cbetas[tid], 0.f), 1.f);
    }

    const float rs2 = g_rs2[tid];
    const float rs3 = g_rs3[tid];
    const float rs4 = (tid < N_OUT) ? g_rs4[tid] : 0.f;

    // Membrane state in registers for the whole run.
    float chm = 0.f, m1 = 0.f, m2 = 0.f, m3 = 0.f, m4 = 0.f;

    const float* xrow = x + (size_t)b * T_STEPS;
    float* o_s1 = out + (size_t)b * N_HID + tid;
    float* o_s2 = o_s1 + SPK_HID;
    float* o_s3 = o_s2 + SPK_HID;
    float* o_s4 = out + 3 * SPK_HID + (size_t)b * N_OUT + tid;
    float* o_m4 = o_s4 + SPK_OUT;

    __syncthreads();  // SMEM weights ready

    for (int t = 0; t < T_STEPS; ++t) {
        // ---------------- cochlea (threads 0..255) ----------------
        bool chs = false;
        if (tid < N_IN) {
            float cur = __fmul_rn(__ldg(xrow + t), wch);
            float rst = (chm > 1.f) ? 1.f : 0.f;
            chm = __fadd_rn(__fadd_rn(__fmul_rn(bch, chm), cur), -rst);
            chs = (chm > 1.f);
        }
        unsigned bal = __ballot_sync(0xffffffffu, chs);
        if (tid < N_IN && lane == 0) s_chmask[warp] = bal;
        int cc = __syncthreads_count(chs);      // barrier #1 (+count)
        if (cc > 0) {
            if (chs) {
                int off = __popc(bal & ltm);
                #pragma unroll
                for (int j = 0; j < 8; ++j) off += (j < warp) ? __popc(s_chmask[j]) : 0;
                s_chlist[off] = tid * N_HID;    // byte offset of weight row k
            }
            __syncthreads();                     // barrier #2
        }

        // ---------------- layer 1: exact integer accumulation ----------------
        float cur1 = 0.f;
        if (cc > 0) {
            int a0 = 0, a1 = 0, a2 = 0, a3 = 0;
            int j = 0;
            for (; j + 4 <= cc; j += 4) {
                int k0 = s_chlist[j + 0];
                int k1 = s_chlist[j + 1];
                int k2 = s_chlist[j + 2];
                int k3 = s_chlist[j + 3];
                a0 += sw1[k0 + tid];
                a1 += sw1[k1 + tid];
                a2 += sw1[k2 + tid];
                a3 += sw1[k3 + tid];
            }
            for (; j < cc; ++j) a0 += sw1[s_chlist[j] + tid];
            // cur = W_MIN * (#spikes) + scale * (sum of levels)   [exact ints]
            cur1 = __fadd_rn(__fmul_rn(0.001f, (float)cc),
                             __fmul_rn(SCALEF, (float)((a0 + a1) + (a2 + a3))));
        }
        float rst1 = (m1 > 1.f) ? 1.f : 0.f;
        m1 = __fadd_rn(__fadd_rn(__fmul_rn(beta1, m1), cur1), -rst1);
        bool s1 = (m1 > 1.f);
        o_s1[(size_t)t * (BATCH * N_HID)] = s1 ? 1.f : 0.f;

        // zeros of s1 -> corrections for layer 2
        unsigned zb = __ballot_sync(0xffffffffu, !s1);
        if (lane == 0) s_zmask[warp] = zb;
        int zc = __syncthreads_count(!s1);       // barrier #3 (+count)
        if (zc > 0 && zc < N_HID) {
            if (!s1) {
                int off = __popc(zb & ltm);
                #pragma unroll
                for (int j = 0; j < 16; ++j) off += (j < warp) ? __popc(s_zmask[j]) : 0;
                s_zlist[off] = tid;
            }
            __syncthreads();
        }

        // ---------------- layer 2: rowsum minus complement ----------------
        float cur2 = 0.f;
        if (zc < N_HID) {                        // zc==512 => input all zero => cur exactly 0
            cur2 = rs2;
            for (int j = 0; j < zc; ++j)
                cur2 = __fadd_rn(cur2, -g_q2T[s_zlist[j] * N_HID + tid]);
        }
        float rst2 = (m2 > 1.f) ? 1.f : 0.f;
        m2 = __fadd_rn(__fadd_rn(__fmul_rn(beta2, m2), cur2), -rst2);
        bool s2 = (m2 > 1.f);
        o_s2[(size_t)t * (BATCH * N_HID)] = s2 ? 1.f : 0.f;

        zb = __ballot_sync(0xffffffffu, !s2);
        if (lane == 0) s_zmask[warp] = zb;
        zc = __syncthreads_count(!s2);           // barrier #4 (+count)
        if (zc > 0 && zc < N_HID) {
            if (!s2) {
                int off = __popc(zb & ltm);
                #pragma unroll
                for (int j = 0; j < 16; ++j) off += (j < warp) ? __popc(s_zmask[j]) : 0;
                s_zlist[off] = tid;
            }
            __syncthreads();
        }

        // ---------------- layer 3 ----------------
        float cur3 = 0.f;
        if (zc < N_HID) {
            cur3 = rs3;
            for (int j = 0; j < zc; ++j)
                cur3 = __fadd_rn(cur3, -g_q3T[s_zlist[j] * N_HID + tid]);
        }
        float rst3 = (m3 > 1.f) ? 1.f : 0.f;
        m3 = __fadd_rn(__fadd_rn(__fmul_rn(beta3, m3), cur3), -rst3);
        bool s3 = (m3 > 1.f);
        o_s3[(size_t)t * (BATCH * N_HID)] = s3 ? 1.f : 0.f;

        zb = __ballot_sync(0xffffffffu, !s3);
        if (lane == 0) s_zmask[warp] = zb;
        zc = __syncthreads_count(!s3);           // barrier #5 (+count)
        if (zc > 0 && zc < N_HID) {
            if (!s3) {
                int off = __popc(zb & ltm);
                #pragma unroll
                for (int j = 0; j < 16; ++j) off += (j < warp) ? __popc(s_zmask[j]) : 0;
                s_zlist[off] = tid;
            }
            __syncthreads();
        }

        // ---------------- layer 4 (threads 0..34) ----------------
        if (tid < N_OUT) {
            float cur4 = 0.f;
            if (zc < N_HID) {
                cur4 = rs4;
                for (int j = 0; j < zc; ++j)
                    cur4 = __fadd_rn(cur4, -g_q4T[s_zlist[j] * N_OUT + tid]);
            }
            float rst4 = (m4 > 1.f) ? 1.f : 0.f;
            m4 = __fadd_rn(__fadd_rn(__fmul_rn(beta4, m4), cur4), -rst4);
            o_s4[(size_t)t * (BATCH * N_OUT)] = (m4 > 1.f) ? 1.f : 0.f;
            o_m4[(size_t)t * (BATCH * N_OUT)] = m4;
        }
    }
}

// ---------------------------------------------------------------------------
// Launcher.  Inputs (metadata order): x, Wch, W1, W2, W3, W4, cochlea_betas,
// beta1, beta2, beta3, beta4.  Output: concat(spk1, spk2, spk3, spk4, mem4),
// each time-major [T, B, F], float32.
// ---------------------------------------------------------------------------
extern "C" void kernel_launch(void* const* d_in, const int* in_sizes, int n_in,
                              void* d_out, int out_size) {
    const float* x   = (const float*)d_in[0];
    const float* Wch = (const float*)d_in[1];
    const float* W1  = (const float*)d_in[2];
    const float* W2  = (const float*)d_in[3];
    const float* W3  = (const float*)d_in[4];
    const float* W4  = (const float*)d_in[5];
    const float* cb  = (const float*)d_in[6];
    const float* b1  = (const float*)d_in[7];
    const float* b2  = (const float*)d_in[8];
    const float* b3  = (const float*)d_in[9];
    const float* b4  = (const float*)d_in[10];
    float* out = (float*)d_out;

    cudaFuncSetAttribute(snn_main, cudaFuncAttributeMaxDynamicSharedMemorySize,
                         N_IN * N_HID);

    prep_quant<<<1024, 256>>>(W1, W2, W3, W4);
    prep_rowsum<<<2, 256>>>();
    snn_main<<<BATCH, 512, N_IN * N_HID>>>(x, Wch, cb, b1, b2, b3, b4, out);
}